// round 16
// baseline (speedup 1.0000x reference)
#include <cuda_runtime.h>
#include <cstdint>

// out[b, l] = x[b, perm[b, l]]   (B=1024, L=16384)
// CONVERGED kernel (R15 + evict_first on the x row load):
// one CTA per row, 1024 threads, 2 CTAs/SM (100% thread occupancy).
// Single 64KB TMA bulk load per row (x read exactly once, evict_first since
// there is zero reuse -> L2 kept free for output write buffering), perm
// prefetched (int4, streaming) during the TMA, SMEM gather, coalesced
// streaming float4 stores. Runs at ~97% of the compulsory 192MB memory floor.

#define THREADS 1024

__global__ __launch_bounds__(THREADS, 2)
void interleave_final2_kernel(const float* __restrict__ x,
                              const int* __restrict__ perm,
                              float* __restrict__ out,
                              int L) {
    extern __shared__ __align__(128) unsigned char smem_raw[];
    float* srow = reinterpret_cast<float*>(smem_raw);
    uint64_t* mbar_p = reinterpret_cast<uint64_t*>(smem_raw + (size_t)L * sizeof(float));
    uint32_t mbar = (uint32_t)__cvta_generic_to_shared(mbar_p);
    uint32_t sdst = (uint32_t)__cvta_generic_to_shared(srow);

    long long row = blockIdx.x;
    const float* xrow = x + row * (long long)L;
    const int*   prow = perm + row * (long long)L;
    float*       orow = out + row * (long long)L;

    int tid = threadIdx.x;
    unsigned bytes = (unsigned)L * 4u;

    // tid 0 inits the mbarrier and immediately issues the TMA (program order
    // covers the init->use dependency; other threads only touch the barrier
    // after the __syncthreads below). TMA issue stays off the CTA-barrier
    // critical path.
    if (tid == 0) {
        asm volatile("mbarrier.init.shared.b64 [%0], %1;"
                     :: "r"(mbar), "r"(1) : "memory");
        asm volatile("fence.proxy.async.shared::cta;" ::: "memory");
        uint64_t policy;
        asm volatile("createpolicy.fractional.L2::evict_first.b64 %0, 1.0;"
                     : "=l"(policy));
        asm volatile("mbarrier.arrive.expect_tx.shared.b64 _, [%0], %1;"
                     :: "r"(mbar), "r"(bytes) : "memory");
        asm volatile("cp.async.bulk.shared::cta.global.mbarrier::complete_tx::bytes"
                     ".L2::cache_hint [%0], [%1], %2, [%3], %4;"
                     :: "r"(sdst), "l"(xrow), "r"(bytes), "r"(mbar), "l"(policy)
                     : "memory");
    }
    __syncthreads();

    // Prefetch perm while the TMA streams the row.
    // L/4 = 4096 int4 = 4 * THREADS exactly. Streaming: read-once.
    const int4* p4 = reinterpret_cast<const int4*>(prow);
    int4 p[4];
    #pragma unroll
    for (int j = 0; j < 4; j++) p[j] = __ldcs(p4 + tid + j * THREADS);

    // Wait for the row (acquire orders subsequent smem reads).
    {
        uint32_t done;
        asm volatile(
            "{\n\t.reg .pred P;\n\t"
            "mbarrier.try_wait.parity.acquire.cta.shared::cta.b64 P, [%1], %2;\n\t"
            "selp.b32 %0, 1, 0, P;\n\t}"
            : "=r"(done) : "r"(mbar), "r"(0u) : "memory");
        if (!done) {
            asm volatile(
                "{\n\t.reg .pred P;\n\t"
                "W_%=:\n\t"
                "mbarrier.try_wait.parity.acquire.cta.shared::cta.b64 P, [%0], %1, 0x989680;\n\t"
                "@P bra.uni D_%=;\n\t"
                "bra.uni W_%=;\n\t"
                "D_%=:\n\t}"
                :: "r"(mbar), "r"(0u) : "memory");
        }
    }

    // Gather from SMEM, coalesced streaming stores.
    float4* o4 = reinterpret_cast<float4*>(orow);
    #pragma unroll
    for (int j = 0; j < 4; j++) {
        float4 o;
        o.x = srow[p[j].x];
        o.y = srow[p[j].y];
        o.z = srow[p[j].z];
        o.w = srow[p[j].w];
        __stcs(o4 + tid + j * THREADS, o);
    }
}

extern "C" void kernel_launch(void* const* d_in, const int* in_sizes, int n_in,
                              void* d_out, int out_size) {
    const float* x   = (const float*)d_in[0];
    const int* perm  = (const int*)d_in[1];
    float* out       = (float*)d_out;

    long long total = (long long)in_sizes[1];
    int B = 1024;
    int L = (int)(total / B);

    size_t smem = (size_t)L * sizeof(float) + 16;
    cudaFuncSetAttribute(interleave_final2_kernel,
                         cudaFuncAttributeMaxDynamicSharedMemorySize, (int)smem);

    interleave_final2_kernel<<<B, THREADS, smem>>>(x, perm, out, L);
}

// round 17
// speedup vs baseline: 1.0018x; 1.0018x over previous
#include <cuda_runtime.h>
#include <cstdint>

// out[b, l] = x[b, perm[b, l]]   (B=1024, L=16384)
// FINAL (= R15, best measured: kernel 28.03us, 6.85 TB/s logical goodput,
// ~97% of the compulsory 192MB memory floor).
// One CTA per row, 1024 threads, 2 CTAs/SM (100% thread occupancy).
// Single 64KB TMA bulk load per row (x read exactly once), issued by tid 0
// ahead of the CTA barrier; perm prefetched (int4, streaming) while the TMA
// streams; SMEM gather; coalesced streaming float4 stores.

#define THREADS 1024

__global__ __launch_bounds__(THREADS, 2)
void interleave_final_kernel(const float* __restrict__ x,
                             const int* __restrict__ perm,
                             float* __restrict__ out,
                             int L) {
    extern __shared__ __align__(128) unsigned char smem_raw[];
    float* srow = reinterpret_cast<float*>(smem_raw);
    uint64_t* mbar_p = reinterpret_cast<uint64_t*>(smem_raw + (size_t)L * sizeof(float));
    uint32_t mbar = (uint32_t)__cvta_generic_to_shared(mbar_p);
    uint32_t sdst = (uint32_t)__cvta_generic_to_shared(srow);

    long long row = blockIdx.x;
    const float* xrow = x + row * (long long)L;
    const int*   prow = perm + row * (long long)L;
    float*       orow = out + row * (long long)L;

    int tid = threadIdx.x;
    unsigned bytes = (unsigned)L * 4u;

    // tid 0 alone inits the mbarrier AND issues the TMA (program order makes
    // the init visible to its own expect_tx/copy). Other threads touch the
    // barrier only after the __syncthreads below, so no init race exists —
    // and the TMA starts without waiting for CTA-wide barrier arrival.
    if (tid == 0) {
        asm volatile("mbarrier.init.shared.b64 [%0], %1;"
                     :: "r"(mbar), "r"(1) : "memory");
        asm volatile("fence.proxy.async.shared::cta;" ::: "memory");
        asm volatile("mbarrier.arrive.expect_tx.shared.b64 _, [%0], %1;"
                     :: "r"(mbar), "r"(bytes) : "memory");
        asm volatile("cp.async.bulk.shared::cta.global.mbarrier::complete_tx::bytes "
                     "[%0], [%1], %2, [%3];"
                     :: "r"(sdst), "l"(xrow), "r"(bytes), "r"(mbar) : "memory");
    }
    __syncthreads();

    // Prefetch perm while the TMA streams the row.
    // L/4 = 4096 int4 = 4 * THREADS exactly. Streaming: read-once.
    const int4* p4 = reinterpret_cast<const int4*>(prow);
    int4 p[4];
    #pragma unroll
    for (int j = 0; j < 4; j++) p[j] = __ldcs(p4 + tid + j * THREADS);

    // Wait for the row (acquire orders subsequent smem reads).
    {
        uint32_t done;
        asm volatile(
            "{\n\t.reg .pred P;\n\t"
            "mbarrier.try_wait.parity.acquire.cta.shared::cta.b64 P, [%1], %2;\n\t"
            "selp.b32 %0, 1, 0, P;\n\t}"
            : "=r"(done) : "r"(mbar), "r"(0u) : "memory");
        if (!done) {
            asm volatile(
                "{\n\t.reg .pred P;\n\t"
                "W_%=:\n\t"
                "mbarrier.try_wait.parity.acquire.cta.shared::cta.b64 P, [%0], %1, 0x989680;\n\t"
                "@P bra.uni D_%=;\n\t"
                "bra.uni W_%=;\n\t"
                "D_%=:\n\t}"
                :: "r"(mbar), "r"(0u) : "memory");
        }
    }

    // Gather from SMEM, coalesced streaming stores.
    float4* o4 = reinterpret_cast<float4*>(orow);
    #pragma unroll
    for (int j = 0; j < 4; j++) {
        float4 o;
        o.x = srow[p[j].x];
        o.y = srow[p[j].y];
        o.z = srow[p[j].z];
        o.w = srow[p[j].w];
        __stcs(o4 + tid + j * THREADS, o);
    }
}

extern "C" void kernel_launch(void* const* d_in, const int* in_sizes, int n_in,
                              void* d_out, int out_size) {
    const float* x   = (const float*)d_in[0];
    const int* perm  = (const int*)d_in[1];
    float* out       = (float*)d_out;

    long long total = (long long)in_sizes[1];
    int B = 1024;
    int L = (int)(total / B);

    size_t smem = (size_t)L * sizeof(float) + 16;
    cudaFuncSetAttribute(interleave_final_kernel,
                         cudaFuncAttributeMaxDynamicSharedMemorySize, (int)smem);

    interleave_final_kernel<<<B, THREADS, smem>>>(x, perm, out, L);
}